// round 3
// baseline (speedup 1.0000x reference)
#include <cuda_runtime.h>
#include <math.h>

#define DIM    4096
#define NH     32
#define HD     128
#define SEQ    4096
#define BATCH  16
#define NSPLIT 8
#define SPLIT_LEN (SEQ / NSPLIT)   // 512

typedef unsigned long long u64;

// ---------------- scratch (no allocs allowed -> __device__ globals) ----------------
__device__ __align__(16) float g_q[BATCH * DIM];
__device__ __align__(16) float g_k[BATCH * DIM];
__device__ __align__(16) float g_v[BATCH * DIM];
__device__ __align__(16) float g_attn[BATCH * DIM];
__device__ __align__(16) float g_po[BATCH * NH * NSPLIT * HD];   // partial outputs
__device__ float g_pm[BATCH * NH * NSPLIT];        // partial max
__device__ float g_pl[BATCH * NH * NSPLIT];        // partial sum(exp)

// packed dual-lane fp32 FMA (Blackwell f32x2 pipe; PTX-only encoding)
__device__ __forceinline__ u64 ffma2(u64 a, u64 b, u64 c) {
    u64 d;
    asm("fma.rn.f32x2 %0, %1, %2, %3;" : "=l"(d) : "l"(a), "l"(b), "l"(c));
    return d;
}

// ---------------- projection: each warp computes 2 output columns x 16 batches -----
__device__ __forceinline__ void proj2(const float* __restrict__ X,
                                      const float* __restrict__ W,
                                      int j0, int lane,
                                      float* __restrict__ out) {
    const ulonglong2* W0 = reinterpret_cast<const ulonglong2*>(W + (size_t)j0 * DIM);
    const ulonglong2* W1 = reinterpret_cast<const ulonglong2*>(W + (size_t)(j0 + 1) * DIM);
    const ulonglong2* X2 = reinterpret_cast<const ulonglong2*>(X);

    u64 a0[BATCH], a1[BATCH];
#pragma unroll
    for (int b = 0; b < BATCH; ++b) { a0[b] = 0ULL; a1[b] = 0ULL; }

#pragma unroll 2
    for (int it = 0; it < DIM / 128; ++it) {       // 32 iterations of 4 floats/lane
        int idx = it * 32 + lane;
        ulonglong2 w0 = W0[idx];
        ulonglong2 w1 = W1[idx];
#pragma unroll
        for (int b = 0; b < BATCH; ++b) {
            ulonglong2 xv = X2[b * (DIM / 4) + idx];
            a0[b] = ffma2(w0.x, xv.x, a0[b]);
            a0[b] = ffma2(w0.y, xv.y, a0[b]);
            a1[b] = ffma2(w1.x, xv.x, a1[b]);
            a1[b] = ffma2(w1.y, xv.y, a1[b]);
        }
    }

#pragma unroll
    for (int b = 0; b < BATCH; ++b) {
        float2 f0 = *reinterpret_cast<float2*>(&a0[b]);
        float2 f1 = *reinterpret_cast<float2*>(&a1[b]);
        float v0 = f0.x + f0.y;
        float v1 = f1.x + f1.y;
#pragma unroll
        for (int off = 16; off > 0; off >>= 1) {
            v0 += __shfl_down_sync(0xffffffffu, v0, off);
            v1 += __shfl_down_sync(0xffffffffu, v1, off);
        }
        if (lane == 0) {
            out[b * DIM + j0]     = v0;
            out[b * DIM + j0 + 1] = v1;
        }
    }
}

// grid = 3*DIM/8 = 1536 blocks, 128 threads; 8 cols/block
__global__ void __launch_bounds__(128) proj_qkv_kernel(const float* __restrict__ x,
                                                       const float* __restrict__ wq,
                                                       const float* __restrict__ wk,
                                                       const float* __restrict__ wv) {
    int warp = threadIdx.x >> 5, lane = threadIdx.x & 31;
    int cg = blockIdx.x * 8 + warp * 2;        // global column 0..12287
    int wsel = cg >> 12;                       // 0=q, 1=k, 2=v
    int j0 = cg & (DIM - 1);
    const float* W = (wsel == 0) ? wq : (wsel == 1) ? wk : wv;
    float* out     = (wsel == 0) ? g_q : (wsel == 1) ? g_k : g_v;
    proj2(x, W, j0, lane, out);
}

// grid = DIM/8 = 512 blocks
__global__ void __launch_bounds__(128) proj_o_kernel(const float* __restrict__ wo,
                                                     float* __restrict__ out) {
    int warp = threadIdx.x >> 5, lane = threadIdx.x & 31;
    int j0 = blockIdx.x * 8 + warp * 2;
    proj2(g_attn, wo, j0, lane, out);
}

// ---------------- flash-decoding split attention ----------------
// grid = (NSPLIT, NH, BATCH) = 4096 blocks, 256 threads
__global__ void __launch_bounds__(256) attn_split_kernel(const float* __restrict__ kc,
                                                         const float* __restrict__ vc) {
    int split = blockIdx.x, h = blockIdx.y, b = blockIdx.z;
    int tid = threadIdx.x, warp = tid >> 5, lane = tid & 31;

    __shared__ float sc[SPLIT_LEN + 1];
    __shared__ __align__(16) float qs[HD];
    __shared__ float redm[8], redl[8];
    __shared__ float osum[HD];

    if (tid < HD) qs[tid] = g_q[b * DIM + h * HD + tid];
    __syncthreads();

    const float scale = 0.08838834764831845f;   // 1/sqrt(128)
    const bool last = (split == NSPLIT - 1);
    const size_t base = (((size_t)b * NH + h) * SEQ + (size_t)split * SPLIT_LEN) * HD;

    float4 q4 = *reinterpret_cast<const float4*>(&qs[lane * 4]);

    // Phase 1: scores. One warp per row; each lane handles 4 of 128 dims.
#pragma unroll 8
    for (int s = warp; s < SPLIT_LEN; s += 8) {
        float4 k4 = *reinterpret_cast<const float4*>(kc + base + (size_t)s * HD + lane * 4);
        float v = q4.x * k4.x + q4.y * k4.y + q4.z * k4.z + q4.w * k4.w;
#pragma unroll
        for (int off = 16; off > 0; off >>= 1) v += __shfl_down_sync(0xffffffffu, v, off);
        if (lane == 0) sc[s] = v * scale;
    }
    if (last && warp == 0) {   // appended new token from k projection
        float4 k4 = *reinterpret_cast<const float4*>(g_k + b * DIM + h * HD + lane * 4);
        float v = q4.x * k4.x + q4.y * k4.y + q4.z * k4.z + q4.w * k4.w;
#pragma unroll
        for (int off = 16; off > 0; off >>= 1) v += __shfl_down_sync(0xffffffffu, v, off);
        if (lane == 0) sc[SPLIT_LEN] = v * scale;
    }
    __syncthreads();

    // Phase 2: partial softmax (max then exp-sum)
    int ns = SPLIT_LEN + (last ? 1 : 0);
    float m = -1e30f;
    for (int s = tid; s < ns; s += 256) m = fmaxf(m, sc[s]);
#pragma unroll
    for (int off = 16; off > 0; off >>= 1) m = fmaxf(m, __shfl_xor_sync(0xffffffffu, m, off));
    if (lane == 0) redm[warp] = m;
    __syncthreads();
    float M = redm[0];
#pragma unroll
    for (int w = 1; w < 8; ++w) M = fmaxf(M, redm[w]);

    float lsum = 0.f;
    for (int s = tid; s < ns; s += 256) {
        float p = __expf(sc[s] - M);
        sc[s] = p;
        lsum += p;
    }
#pragma unroll
    for (int off = 16; off > 0; off >>= 1) lsum += __shfl_xor_sync(0xffffffffu, lsum, off);
    if (lane == 0) redl[warp] = lsum;
    __syncthreads();   // also orders sc[] writes before phase 3 reads

    // Phase 3: o[d] = sum_s p[s] * V[s][d]. 2 rows in flight (tid>>7), coalesced over d.
    int d = tid & (HD - 1);
    int sh = tid >> 7;
    const float* Vp = vc + base + d;
    float acc = 0.f;
#pragma unroll 16
    for (int s = sh; s < SPLIT_LEN; s += 2)
        acc += sc[s] * Vp[(size_t)s * HD];

    if (sh == 1) osum[d] = acc;
    __syncthreads();
    int pi = (b * NH + h) * NSPLIT + split;
    if (sh == 0) {
        float tot = acc + osum[d];
        if (last) tot += sc[SPLIT_LEN] * g_v[b * DIM + h * HD + d];
        g_po[pi * HD + d] = tot;
    }
    if (tid == 0) {
        float L = 0.f;
#pragma unroll
        for (int w = 0; w < 8; ++w) L += redl[w];
        g_pm[pi] = M;
        g_pl[pi] = L;
    }
}

// grid = BATCH*NH = 512 blocks, 128 threads
__global__ void __launch_bounds__(128) attn_combine_kernel() {
    int bh = blockIdx.x;
    int d = threadIdx.x;
    int b = bh >> 5, h = bh & 31;

    float ms[NSPLIT];
    float M = -1e30f;
#pragma unroll
    for (int i = 0; i < NSPLIT; ++i) { ms[i] = g_pm[bh * NSPLIT + i]; M = fmaxf(M, ms[i]); }
    float L = 0.f, w[NSPLIT];
#pragma unroll
    for (int i = 0; i < NSPLIT; ++i) { w[i] = __expf(ms[i] - M); L += g_pl[bh * NSPLIT + i] * w[i]; }
    float o = 0.f;
#pragma unroll
    for (int i = 0; i < NSPLIT; ++i) o += g_po[(bh * NSPLIT + i) * HD + d] * w[i];
    g_attn[b * DIM + h * HD + d] = o / L;
}

// ---------------- launch ----------------
extern "C" void kernel_launch(void* const* d_in, const int* in_sizes, int n_in,
                              void* d_out, int out_size) {
    const float* x  = (const float*)d_in[0];
    const float* kc = (const float*)d_in[1];
    const float* vc = (const float*)d_in[2];
    const float* wq = (const float*)d_in[3];
    const float* wk = (const float*)d_in[4];
    const float* wv = (const float*)d_in[5];
    const float* wo = (const float*)d_in[6];
    float* out = (float*)d_out;

    proj_qkv_kernel<<<3 * DIM / 8, 128>>>(x, wq, wk, wv);
    attn_split_kernel<<<dim3(NSPLIT, NH, BATCH), 256>>>(kc, vc);
    attn_combine_kernel<<<BATCH * NH, 128>>>();
    proj_o_kernel<<<DIM / 8, 128>>>(wo, out);
}

// round 4
// speedup vs baseline: 1.0781x; 1.0781x over previous
#include <cuda_runtime.h>
#include <math.h>

#define DIM    4096
#define NH     32
#define HD     128
#define SEQ    4096
#define BATCH  16
#define NSPLIT 8
#define SPLIT_LEN (SEQ / NSPLIT)   // 512

// ---------------- scratch (no allocs allowed -> __device__ globals) ----------------
__device__ __align__(16) float g_q[BATCH * DIM];
__device__ __align__(16) float g_k[BATCH * DIM];
__device__ __align__(16) float g_v[BATCH * DIM];
__device__ __align__(16) float g_attn[BATCH * DIM];
__device__ __align__(16) float g_po[BATCH * NH * NSPLIT * HD];   // partial outputs
__device__ float g_pm[BATCH * NH * NSPLIT];        // partial max
__device__ float g_pl[BATCH * NH * NSPLIT];        // partial sum(exp)

// ---------------- projection: each warp computes ONE output column x 16 batches ----
__device__ __forceinline__ void proj1(const float* __restrict__ X,
                                      const float* __restrict__ W,
                                      int j, int lane,
                                      float* __restrict__ out) {
    const float4* Wp = reinterpret_cast<const float4*>(W + (size_t)j * DIM);
    const float4* X4 = reinterpret_cast<const float4*>(X);

    float a[BATCH];
#pragma unroll
    for (int b = 0; b < BATCH; ++b) a[b] = 0.f;

#pragma unroll 4
    for (int it = 0; it < DIM / 128; ++it) {       // 32 iterations, 4 floats/lane
        int idx = it * 32 + lane;
        float4 w = Wp[idx];
#pragma unroll
        for (int b = 0; b < BATCH; ++b) {
            float4 xv = X4[b * (DIM / 4) + idx];
            a[b] += w.x * xv.x + w.y * xv.y + w.z * xv.z + w.w * xv.w;
        }
    }

#pragma unroll
    for (int b = 0; b < BATCH; ++b) {
        float v = a[b];
#pragma unroll
        for (int off = 16; off > 0; off >>= 1)
            v += __shfl_down_sync(0xffffffffu, v, off);
        if (lane == 0) out[b * DIM + j] = v;
    }
}

// grid = 3*DIM/8 = 1536 blocks, 256 threads; 8 cols/block (1 per warp)
__global__ void __launch_bounds__(256) proj_qkv_kernel(const float* __restrict__ x,
                                                       const float* __restrict__ wq,
                                                       const float* __restrict__ wk,
                                                       const float* __restrict__ wv) {
    int warp = threadIdx.x >> 5, lane = threadIdx.x & 31;
    int cg = blockIdx.x * 8 + warp;            // global column 0..12287
    int wsel = cg >> 12;                       // 0=q, 1=k, 2=v
    int j = cg & (DIM - 1);
    const float* W = (wsel == 0) ? wq : (wsel == 1) ? wk : wv;
    float* out     = (wsel == 0) ? g_q : (wsel == 1) ? g_k : g_v;
    proj1(x, W, j, lane, out);
}

// grid = DIM/8 = 512 blocks
__global__ void __launch_bounds__(256) proj_o_kernel(const float* __restrict__ wo,
                                                     float* __restrict__ out) {
    int warp = threadIdx.x >> 5, lane = threadIdx.x & 31;
    int j = blockIdx.x * 8 + warp;
    proj1(g_attn, wo, j, lane, out);
}

// ---------------- flash-decoding split attention ----------------
// grid = (NSPLIT, NH, BATCH) = 4096 blocks, 256 threads
__global__ void __launch_bounds__(256) attn_split_kernel(const float* __restrict__ kc,
                                                         const float* __restrict__ vc) {
    int split = blockIdx.x, h = blockIdx.y, b = blockIdx.z;
    int tid = threadIdx.x, warp = tid >> 5, lane = tid & 31;

    __shared__ float sc[SPLIT_LEN + 1];
    __shared__ __align__(16) float qs[HD];
    __shared__ float redm[8], redl[8];
    __shared__ float osum[HD];

    if (tid < HD) qs[tid] = g_q[b * DIM + h * HD + tid];
    __syncthreads();

    const float scale = 0.08838834764831845f;   // 1/sqrt(128)
    const bool last = (split == NSPLIT - 1);
    const size_t base = (((size_t)b * NH + h) * SEQ + (size_t)split * SPLIT_LEN) * HD;

    float4 q4 = *reinterpret_cast<const float4*>(&qs[lane * 4]);

    // Phase 1: scores. One warp per row; each lane handles 4 of 128 dims.
#pragma unroll 8
    for (int s = warp; s < SPLIT_LEN; s += 8) {
        float4 k4 = *reinterpret_cast<const float4*>(kc + base + (size_t)s * HD + lane * 4);
        float v = q4.x * k4.x + q4.y * k4.y + q4.z * k4.z + q4.w * k4.w;
#pragma unroll
        for (int off = 16; off > 0; off >>= 1) v += __shfl_down_sync(0xffffffffu, v, off);
        if (lane == 0) sc[s] = v * scale;
    }
    if (last && warp == 0) {   // appended new token from k projection
        float4 k4 = *reinterpret_cast<const float4*>(g_k + b * DIM + h * HD + lane * 4);
        float v = q4.x * k4.x + q4.y * k4.y + q4.z * k4.z + q4.w * k4.w;
#pragma unroll
        for (int off = 16; off > 0; off >>= 1) v += __shfl_down_sync(0xffffffffu, v, off);
        if (lane == 0) sc[SPLIT_LEN] = v * scale;
    }
    __syncthreads();

    // Phase 2: partial softmax (max then exp-sum)
    int ns = SPLIT_LEN + (last ? 1 : 0);
    float m = -1e30f;
    for (int s = tid; s < ns; s += 256) m = fmaxf(m, sc[s]);
#pragma unroll
    for (int off = 16; off > 0; off >>= 1) m = fmaxf(m, __shfl_xor_sync(0xffffffffu, m, off));
    if (lane == 0) redm[warp] = m;
    __syncthreads();
    float M = redm[0];
#pragma unroll
    for (int w = 1; w < 8; ++w) M = fmaxf(M, redm[w]);

    float lsum = 0.f;
    for (int s = tid; s < ns; s += 256) {
        float p = __expf(sc[s] - M);
        sc[s] = p;
        lsum += p;
    }
#pragma unroll
    for (int off = 16; off > 0; off >>= 1) lsum += __shfl_xor_sync(0xffffffffu, lsum, off);
    if (lane == 0) redl[warp] = lsum;
    __syncthreads();   // also orders sc[] writes before phase 3 reads

    // Phase 3: o[d] = sum_s p[s] * V[s][d]. 2 rows in flight (tid>>7), coalesced over d.
    int d = tid & (HD - 1);
    int sh = tid >> 7;
    const float* Vp = vc + base + d;
    float acc = 0.f;
#pragma unroll 16
    for (int s = sh; s < SPLIT_LEN; s += 2)
        acc += sc[s] * Vp[(size_t)s * HD];

    if (sh == 1) osum[d] = acc;
    __syncthreads();
    int pi = (b * NH + h) * NSPLIT + split;
    if (sh == 0) {
        float tot = acc + osum[d];
        if (last) tot += sc[SPLIT_LEN] * g_v[b * DIM + h * HD + d];
        g_po[pi * HD + d] = tot;
    }
    if (tid == 0) {
        float L = 0.f;
#pragma unroll
        for (int w = 0; w < 8; ++w) L += redl[w];
        g_pm[pi] = M;
        g_pl[pi] = L;
    }
}

// grid = BATCH*NH = 512 blocks, 128 threads
__global__ void __launch_bounds__(128) attn_combine_kernel() {
    int bh = blockIdx.x;
    int d = threadIdx.x;
    int b = bh >> 5, h = bh & 31;

    float ms[NSPLIT];
    float M = -1e30f;
#pragma unroll
    for (int i = 0; i < NSPLIT; ++i) { ms[i] = g_pm[bh * NSPLIT + i]; M = fmaxf(M, ms[i]); }
    float L = 0.f, w[NSPLIT];
#pragma unroll
    for (int i = 0; i < NSPLIT; ++i) { w[i] = __expf(ms[i] - M); L += g_pl[bh * NSPLIT + i] * w[i]; }
    float o = 0.f;
#pragma unroll
    for (int i = 0; i < NSPLIT; ++i) o += g_po[(bh * NSPLIT + i) * HD + d] * w[i];
    g_attn[b * DIM + h * HD + d] = o / L;
}

// ---------------- launch ----------------
extern "C" void kernel_launch(void* const* d_in, const int* in_sizes, int n_in,
                              void* d_out, int out_size) {
    const float* x  = (const float*)d_in[0];
    const float* kc = (const float*)d_in[1];
    const float* vc = (const float*)d_in[2];
    const float* wq = (const float*)d_in[3];
    const float* wk = (const float*)d_in[4];
    const float* wv = (const float*)d_in[5];
    const float* wo = (const float*)d_in[6];
    float* out = (float*)d_out;

    proj_qkv_kernel<<<3 * DIM / 8, 256>>>(x, wq, wk, wv);
    attn_split_kernel<<<dim3(NSPLIT, NH, BATCH), 256>>>(kc, vc);
    attn_combine_kernel<<<BATCH * NH, 128>>>();
    proj_o_kernel<<<DIM / 8, 256>>>(wo, out);
}